// round 1
// baseline (speedup 1.0000x reference)
#include <cuda_runtime.h>
#include <cuda_bf16.h>
#include <cstdint>

#define EPS_F 0.01f

// Problem shape (fixed by the reference setup_inputs)
constexpr int B = 16;
constexpr int H = 1024;
constexpr int W = 1024;

// Tiling: 32x8 threads, 4 pixels per thread in x => 128x8 output tile
constexpr int TX = 32;
constexpr int TY = 8;
constexpr int PX = 4;
constexpr int TILE_W = TX * PX;   // 128
constexpr int TILE_H = TY;        // 8
constexpr int SH_W = TILE_W + 2;  // 130
constexpr int SH_H = TILE_H + 2;  // 10

__global__ __launch_bounds__(TX * TY) void detection_head_kernel(
    const float* __restrict__ seg,   // [B, 2, H, W]
    float* __restrict__ out)         // [B*H*W] xnms, then [B*2*H*W] seg copy
{
    __shared__ float sx[SH_H][SH_W];

    const int b   = blockIdx.z;
    const int ty0 = blockIdx.y * TILE_H;
    const int tx0 = blockIdx.x * TILE_W;

    const float* __restrict__ c0 = seg + (size_t)b * 2 * H * W;
    const float* __restrict__ c1 = c0 + (size_t)H * W;

    const int tid = threadIdx.y * TX + threadIdx.x;

    // Fill shared tile of raw x = c1 - c0 - EPS, with 1-pixel halo.
    // Out-of-image halo = 0.0f (exact: the pool is relu'd and zero-floored,
    // so xm = max(0, max of raw neighbor x) and 0 is the identity).
    #pragma unroll
    for (int idx = tid; idx < SH_H * SH_W; idx += TX * TY) {
        const int r  = idx / SH_W;
        const int c  = idx - r * SH_W;
        const int gy = ty0 - 1 + r;
        const int gx = tx0 - 1 + c;
        float v = 0.0f;
        if ((unsigned)gy < (unsigned)H && (unsigned)gx < (unsigned)W) {
            const int g = gy * W + gx;
            v = c1[g] - c0[g] - EPS_F;
        }
        sx[r][c] = v;
    }
    __syncthreads();

    const int r     = threadIdx.y + 1;
    const int cbase = threadIdx.x * PX + 1;
    const int gy    = ty0 + threadIdx.y;
    const int gx    = tx0 + threadIdx.x * PX;

    float4 res;
    float* resp = &res.x;
    #pragma unroll
    for (int i = 0; i < PX; i++) {
        const int c = cbase + i;
        const float x = sx[r][c];
        float m = 0.0f;
        m = fmaxf(m, sx[r - 1][c - 1]);
        m = fmaxf(m, sx[r - 1][c    ]);
        m = fmaxf(m, sx[r - 1][c + 1]);
        m = fmaxf(m, sx[r    ][c - 1]);
        m = fmaxf(m, sx[r    ][c + 1]);
        m = fmaxf(m, sx[r + 1][c - 1]);
        m = fmaxf(m, sx[r + 1][c    ]);
        m = fmaxf(m, sx[r + 1][c + 1]);
        resp[i] = (x > m) ? x : 0.0f;
    }

    // xnms write (vectorized, aligned: gx % 4 == 0, W % 4 == 0)
    const size_t g = (size_t)gy * W + gx;
    *(float4*)(out + (size_t)b * H * W + g) = res;

    // Fused segmentation copy: re-read own float4 of c0/c1 (L1 hits — same
    // lines were just read while filling shared) and write to the copy region.
    const float4 v0 = *(const float4*)(c0 + g);
    const float4 v1 = *(const float4*)(c1 + g);
    float* __restrict__ oseg = out + (size_t)B * H * W + (size_t)b * 2 * H * W;
    *(float4*)(oseg + g)                   = v0;
    *(float4*)(oseg + (size_t)H * W + g)   = v1;
}

extern "C" void kernel_launch(void* const* d_in, const int* in_sizes, int n_in,
                              void* d_out, int out_size)
{
    const float* seg = (const float*)d_in[0];
    float* out = (float*)d_out;

    dim3 block(TX, TY, 1);
    dim3 grid(W / TILE_W, H / TILE_H, B);  // 8 x 128 x 16
    detection_head_kernel<<<grid, block>>>(seg, out);
}

// round 2
// speedup vs baseline: 1.2441x; 1.2441x over previous
#include <cuda_runtime.h>
#include <cuda_bf16.h>
#include <cstdint>

#define EPS_F 0.01f

constexpr int B = 16;
constexpr int H = 1024;
constexpr int W = 1024;

// Tile: 128 cols x 16 rows per CTA. Block 32x8 = 256 threads.
// Each thread computes a 4-wide x 2-high output block.
constexpr int TX = 32;
constexpr int TY = 8;
constexpr int TILE_W = 128;
constexpr int TILE_H = 16;

// Shared region: rows ty0-1 .. ty0+16 (18 rows), cols tx0-4 .. tx0+131 (136 cols)
// smem col s corresponds to global col tx0 - 4 + s. Needed cols tx0-1..tx0+128 => s in [3,132].
constexpr int SH_H = TILE_H + 2;        // 18
constexpr int SH_W = 136;               // 34 float4 per row
constexpr int F4_PER_ROW = SH_W / 4;    // 34
constexpr int FILL_TASKS = SH_H * F4_PER_ROW;  // 612

__device__ __forceinline__ float fmax3(float a, float b, float c) {
    return fmaxf(fmaxf(a, b), c);
}

__global__ __launch_bounds__(TX * TY, 6) void detection_head_kernel(
    const float* __restrict__ seg,   // [B, 2, H, W]
    float* __restrict__ out)         // [B*H*W] xnms | [B*2*H*W] seg copy
{
    __shared__ float sx[SH_H][SH_W];

    const int b   = blockIdx.z;
    const int ty0 = blockIdx.y * TILE_H;
    const int tx0 = blockIdx.x * TILE_W;

    const float* __restrict__ c0 = seg + (size_t)b * 2 * H * W;
    const float* __restrict__ c1 = c0 + (size_t)H * W;

    const int tid = threadIdx.y * TX + threadIdx.x;

    // ---- Fill: pure float4 loads, float4 smem stores (conflict-free) ----
    // Out-of-image -> 0.0f (exact: pool is relu'd + zero-floored, so
    // xm = max(0, max of raw neighbor x) and 0 is the identity).
    #pragma unroll
    for (int idx = tid; idx < FILL_TASKS; idx += TX * TY) {
        const unsigned row = (unsigned)idx / F4_PER_ROW;       // const divide -> mul/shift
        const unsigned col = (unsigned)idx - row * F4_PER_ROW; // 0..33
        const int gy = ty0 - 1 + (int)row;
        const int gx = tx0 - 4 + (int)(col * 4);               // 16B aligned
        float4 v = make_float4(0.f, 0.f, 0.f, 0.f);
        // gx is a multiple of 4; either fully in [0, W) or fully out.
        if ((unsigned)gy < (unsigned)H && (unsigned)gx < (unsigned)W) {
            const size_t g = (size_t)gy * W + gx;
            const float4 a = *(const float4*)(c0 + g);
            const float4 bb = *(const float4*)(c1 + g);
            v.x = bb.x - a.x - EPS_F;
            v.y = bb.y - a.y - EPS_F;
            v.z = bb.z - a.z - EPS_F;
            v.w = bb.w - a.w - EPS_F;
        }
        *(float4*)&sx[row][col * 4] = v;
    }
    __syncthreads();

    // ---- Compute: thread (tx,ty) -> output rows yr0=2*ty, yr0+1; cols 4*tx..4*tx+3 ----
    const int yr0 = threadIdx.y * 2;         // local row 0..14
    const int lc  = threadIdx.x * 4;         // local col 0..124
    // smem rows yr0+0..yr0+3 correspond to global rows ty0+yr0-1 .. ty0+yr0+2
    // smem col window needed: s in [lc+3, lc+8]; load aligned f4 at s = lc, lc+4, lc+8.

    float r0[12], r1[12], r2[12], r3[12];
    #pragma unroll
    for (int k = 0; k < 3; k++) {
        *(float4*)&r0[k * 4] = *(const float4*)&sx[yr0 + 0][lc + k * 4];
        *(float4*)&r1[k * 4] = *(const float4*)&sx[yr0 + 1][lc + k * 4];
        *(float4*)&r2[k * 4] = *(const float4*)&sx[yr0 + 2][lc + k * 4];
        *(float4*)&r3[k * 4] = *(const float4*)&sx[yr0 + 3][lc + k * 4];
    }

    // Window indices w = 3..8 within r*[12] correspond to cols lc-1 .. lc+4.
    float v3t[6], v2t[6], v3b[6], v2b[6];
    #pragma unroll
    for (int j = 0; j < 6; j++) {
        const int w = j + 3;
        const float a = r0[w], bb = r1[w], c = r2[w], d = r3[w];
        v3t[j] = fmax3(a, bb, c);
        v2t[j] = fmaxf(a, c);
        v3b[j] = fmax3(bb, c, d);
        v2b[j] = fmaxf(bb, d);
    }

    float4 ot, ob;
    float* otp = &ot.x;
    float* obp = &ob.x;
    #pragma unroll
    for (int i = 0; i < 4; i++) {
        const int j = i + 1;            // center in v-arrays
        const int w = i + 4;            // center in row arrays
        float mt = fmax3(v3t[j - 1], v2t[j], v3t[j + 1]);
        mt = fmaxf(mt, 0.0f);
        float mb = fmax3(v3b[j - 1], v2b[j], v3b[j + 1]);
        mb = fmaxf(mb, 0.0f);
        const float xt = r1[w];
        const float xb = r2[w];
        otp[i] = (xt > mt) ? xt : 0.0f;
        obp[i] = (xb > mb) ? xb : 0.0f;
    }

    // ---- Stores: streaming (never re-read) ----
    const int gy = ty0 + yr0;
    const int gx = tx0 + lc;
    const size_t g0 = (size_t)gy * W + gx;
    const size_t g1 = g0 + W;
    float* __restrict__ oxn = out + (size_t)b * H * W;
    __stcs((float4*)(oxn + g0), ot);
    __stcs((float4*)(oxn + g1), ob);

    // ---- Fused seg copy: re-read own float4s (L1/L2 hits) + streaming store ----
    float* __restrict__ oseg = out + (size_t)B * H * W + (size_t)b * 2 * H * W;
    const float4 a0 = *(const float4*)(c0 + g0);
    const float4 a1 = *(const float4*)(c0 + g1);
    const float4 b0 = *(const float4*)(c1 + g0);
    const float4 b1 = *(const float4*)(c1 + g1);
    __stcs((float4*)(oseg + g0), a0);
    __stcs((float4*)(oseg + g1), a1);
    __stcs((float4*)(oseg + (size_t)H * W + g0), b0);
    __stcs((float4*)(oseg + (size_t)H * W + g1), b1);
}

extern "C" void kernel_launch(void* const* d_in, const int* in_sizes, int n_in,
                              void* d_out, int out_size)
{
    const float* seg = (const float*)d_in[0];
    float* out = (float*)d_out;

    dim3 block(TX, TY, 1);
    dim3 grid(W / TILE_W, H / TILE_H, B);  // 8 x 64 x 16
    detection_head_kernel<<<grid, block>>>(seg, out);
}

// round 3
// speedup vs baseline: 1.3407x; 1.0776x over previous
#include <cuda_runtime.h>
#include <cuda_bf16.h>
#include <cstdint>

#define EPS_F 0.01f

constexpr int B = 16;
constexpr int H = 1024;
constexpr int W = 1024;

// Tile: 128 cols x 16 rows per CTA. Block 32x8 = 256 threads.
// Each thread computes a 4-wide x 2-high output block. Warp = one thread-row.
constexpr int TX = 32;
constexpr int TY = 8;
constexpr int TILE_W = 128;
constexpr int TILE_H = 16;

// smem: rows ty0-1..ty0+16 (18), cols tx0-4..tx0+131 (136 = 34 float4)
constexpr int SH_H = TILE_H + 2;        // 18
constexpr int SH_W = 136;
constexpr int F4_PER_ROW = SH_W / 4;    // 34
constexpr int FILL_TASKS = SH_H * F4_PER_ROW;  // 612

__device__ __forceinline__ float fmax3(float a, float b, float c) {
    return fmaxf(fmaxf(a, b), c);
}

__global__ __launch_bounds__(TX * TY, 6) void detection_head_kernel(
    const float* __restrict__ seg,   // [B, 2, H, W]
    float* __restrict__ out)         // [B*H*W] xnms | [B*2*H*W] seg copy
{
    __shared__ float sx[SH_H][SH_W];

    const int b   = blockIdx.z;
    const int ty0 = blockIdx.y * TILE_H;
    const int tx0 = blockIdx.x * TILE_W;

    const float* __restrict__ c0 = seg + (size_t)b * 2 * H * W;
    const float* __restrict__ c1 = c0 + (size_t)H * W;
    float* __restrict__ oseg = out + (size_t)B * H * W + (size_t)b * 2 * H * W;

    const int tid = threadIdx.y * TX + threadIdx.x;

    // ---- Fill smem with x = c1 - c0 - EPS (halo -> 0, exact: pool is
    // relu'd + zero-floored) AND stream the seg copy for interior pixels. ----
    #pragma unroll
    for (int idx = tid; idx < FILL_TASKS; idx += TX * TY) {
        const unsigned row = (unsigned)idx / F4_PER_ROW;       // 0..17
        const unsigned col = (unsigned)idx - row * F4_PER_ROW; // 0..33
        const int gy = ty0 - 1 + (int)row;
        const int gx = tx0 - 4 + (int)(col * 4);               // 16B aligned
        float4 v = make_float4(0.f, 0.f, 0.f, 0.f);
        if ((unsigned)gy < (unsigned)H && (unsigned)gx < (unsigned)W) {
            const size_t g = (size_t)gy * W + gx;
            const float4 a  = *(const float4*)(c0 + g);
            const float4 bb = *(const float4*)(c1 + g);
            v.x = bb.x - a.x - EPS_F;
            v.y = bb.y - a.y - EPS_F;
            v.z = bb.z - a.z - EPS_F;
            v.w = bb.w - a.w - EPS_F;
            // Interior of this CTA's tile: written exactly once chip-wide.
            if (row >= 1u && row <= (unsigned)TILE_H &&
                col >= 1u && col <= (unsigned)(TILE_W / 4)) {
                __stcs((float4*)(oseg + g), a);
                __stcs((float4*)(oseg + (size_t)H * W + g), bb);
            }
        }
        *(float4*)&sx[row][col * 4] = v;
    }
    __syncthreads();

    // ---- Compute: per row, one center LDS.128 + shfl for halo elements ----
    const int yr0 = threadIdx.y * 2;      // local row 0..14
    const int lc  = threadIdx.x * 4;      // local col 0..124
    const unsigned FULL = 0xFFFFFFFFu;

    // 4 smem rows (yr0..yr0+3) = global rows ty0+yr0-1 .. ty0+yr0+2.
    // Per row: 6 values at cols lc+3 .. lc+8 (j = 0..5; centers j=1..4).
    float rw[4][6];
    #pragma unroll
    for (int r = 0; r < 4; r++) {
        const float4 ce = *(const float4*)&sx[yr0 + r][lc + 4];
        float lft = __shfl_up_sync(FULL, ce.w, 1);    // lane tx-1's last elem
        float rgt = __shfl_down_sync(FULL, ce.x, 1);  // lane tx+1's first elem
        if (threadIdx.x == 0)  lft = sx[yr0 + r][3];
        if (threadIdx.x == 31) rgt = sx[yr0 + r][132];
        rw[r][0] = lft;
        rw[r][1] = ce.x; rw[r][2] = ce.y; rw[r][3] = ce.z; rw[r][4] = ce.w;
        rw[r][5] = rgt;
    }

    // Column maxes (separable hole-pool)
    float v3t[6], v2t[6], v3b[6], v2b[6];
    #pragma unroll
    for (int j = 0; j < 6; j++) {
        const float a = rw[0][j], bb = rw[1][j], c = rw[2][j], d = rw[3][j];
        v3t[j] = fmax3(a, bb, c);
        v2t[j] = fmaxf(a, c);
        v3b[j] = fmax3(bb, c, d);
        v2b[j] = fmaxf(bb, d);
    }

    float4 ot, ob;
    float* otp = &ot.x;
    float* obp = &ob.x;
    #pragma unroll
    for (int i = 0; i < 4; i++) {
        const int j = i + 1;
        float mt = fmax3(v3t[j - 1], v2t[j], v3t[j + 1]);
        mt = fmaxf(mt, 0.0f);
        float mb = fmax3(v3b[j - 1], v2b[j], v3b[j + 1]);
        mb = fmaxf(mb, 0.0f);
        const float xt = rw[1][j];
        const float xb = rw[2][j];
        otp[i] = (xt > mt) ? xt : 0.0f;
        obp[i] = (xb > mb) ? xb : 0.0f;
    }

    // ---- xnms streaming stores ----
    const int gy = ty0 + yr0;
    const int gx = tx0 + lc;
    const size_t g0 = (size_t)gy * W + gx;
    float* __restrict__ oxn = out + (size_t)b * H * W;
    __stcs((float4*)(oxn + g0), ot);
    __stcs((float4*)(oxn + g0 + W), ob);
}

extern "C" void kernel_launch(void* const* d_in, const int* in_sizes, int n_in,
                              void* d_out, int out_size)
{
    const float* seg = (const float*)d_in[0];
    float* out = (float*)d_out;

    dim3 block(TX, TY, 1);
    dim3 grid(W / TILE_W, H / TILE_H, B);  // 8 x 64 x 16
    detection_head_kernel<<<grid, block>>>(seg, out);
}